// round 7
// baseline (speedup 1.0000x reference)
#include <cuda_runtime.h>
#include <cstdint>

#define BATCH 8
#define IN_F 4096
#define OUT_F 12288
#define GS 128
#define NG 32
#define OPW 4            // outputs per warp
#define WPB 4            // warps per CTA
#define TPB (WPB * 32)
#define OPC (WPB * OPW)  // 16 outputs per CTA
#define NSTG 3           // pipeline stages
#define STG_BYTES (OPC * GS * 4)   // 8192 B per stage

typedef unsigned long long u64;

__device__ float g_sx[BATCH * NG];

__device__ __forceinline__ u64 pack2(float lo, float hi) {
    u64 r; asm("mov.b64 %0, {%1, %2};" : "=l"(r) : "f"(lo), "f"(hi)); return r;
}
__device__ __forceinline__ void unpack2(u64 v, float& lo, float& hi) {
    asm("mov.b64 {%0, %1}, %2;" : "=f"(lo), "=f"(hi) : "l"(v));
}
__device__ __forceinline__ u64 fma2(u64 a, u64 b, u64 c) {
    u64 d; asm("fma.rn.f32x2 %0, %1, %2, %3;" : "=l"(d) : "l"(a), "l"(b), "l"(c)); return d;
}
__device__ __forceinline__ u64 mul2(u64 a, u64 b) {
    u64 d; asm("mul.rn.f32x2 %0, %1, %2;" : "=l"(d) : "l"(a), "l"(b)); return d;
}
__device__ __forceinline__ ulonglong2 ldg_x2(const float* p) {
    ulonglong2 v;
    asm("ld.global.nc.L1::evict_last.v2.u64 {%0,%1}, [%2];"
        : "=l"(v.x), "=l"(v.y) : "l"(p));
    return v;
}
__device__ __forceinline__ void mbar_init(uint32_t a, unsigned cnt) {
    asm volatile("mbarrier.init.shared.b64 [%0], %1;" :: "r"(a), "r"(cnt) : "memory");
}
__device__ __forceinline__ void mbar_arrive(uint32_t a) {
    asm volatile("mbarrier.arrive.shared.b64 _, [%0];" :: "r"(a) : "memory");
}
__device__ __forceinline__ void mbar_expect_tx(uint32_t a, unsigned bytes) {
    asm volatile("mbarrier.arrive.expect_tx.shared.b64 _, [%0], %1;"
                 :: "r"(a), "r"(bytes) : "memory");
}
__device__ __forceinline__ void mbar_wait(uint32_t a, int phase) {
    asm volatile(
        "{\n\t.reg .pred P;\n"
        "W_%=:\n\t"
        "mbarrier.try_wait.parity.shared.b64 P, [%0], %1;\n\t"
        "@!P bra W_%=;\n\t}"
        :: "r"(a), "r"(phase) : "memory");
}
__device__ __forceinline__ void bulk_ld(uint32_t dst, const void* src,
                                        unsigned bytes, uint32_t mbar) {
    asm volatile(
        "cp.async.bulk.shared::cluster.global.mbarrier::complete_tx::bytes "
        "[%0], [%1], %2, [%3];"
        :: "r"(dst), "l"(src), "r"(bytes), "r"(mbar) : "memory");
}

// ---- prekernel: Sx[b][g] = sum of x over group g ----
__global__ void prep_kernel(const float* __restrict__ x) {
    const int gt   = blockIdx.x * blockDim.x + threadIdx.x;
    const int w    = gt >> 5;
    const int lane = gt & 31;
    const int base = (w >> 5) * IN_F + (w & 31) * GS + lane * 4;
    float4 v = __ldg((const float4*)(x + base));
    float s = (v.x + v.y) + (v.z + v.w);
    #pragma unroll
    for (int off = 16; off > 0; off >>= 1)
        s += __shfl_xor_sync(0xffffffffu, s, off);
    if (lane == 0) g_sx[w] = s;
}

// ---- main kernel ----
__global__ void __launch_bounds__(TPB, 4)
w4a32_main(const float* __restrict__ x, const int* __restrict__ qw,
           const float* __restrict__ sc, const float* __restrict__ zr,
           float* __restrict__ out)
{
    __shared__ __align__(128) int ws[NSTG * OPC * GS];   // 24 KB weight stages
    __shared__ __align__(8) unsigned long long mbar[2 * NSTG];  // full[s], empty[s]
    __shared__ float bounce[WPB][OPW * BATCH];

    const int tid    = threadIdx.x;
    const int warp   = tid >> 5;
    const int lane   = tid & 31;
    const int cta_n0 = blockIdx.x * OPC;
    const int n0     = cta_n0 + warp * OPW;
    const int klo    = lane * 4;

    const uint32_t ws_base   = (uint32_t)__cvta_generic_to_shared(ws);
    const uint32_t full_base = (uint32_t)__cvta_generic_to_shared(&mbar[0]);
    const uint32_t empt_base = (uint32_t)__cvta_generic_to_shared(&mbar[NSTG]);
    const char* qsrc = (const char*)qw + (size_t)cta_n0 * IN_F * 4;

    if (tid == 0) {
        #pragma unroll
        for (int s = 0; s < NSTG; ++s) {
            mbar_init(full_base + s * 8, 1);
            mbar_init(empt_base + s * 8, TPB);
        }
        asm volatile("fence.proxy.async.shared::cta;" ::: "memory");
    }
    __syncthreads();

    // producer: issue a weight tile (16 rows x 512B) for group g into stage st
    auto issue = [&](int g, int st) {
        const uint32_t mb = full_base + st * 8;
        mbar_expect_tx(mb, STG_BYTES);
        const char* src = qsrc + (size_t)g * 512;
        uint32_t dst = ws_base + st * STG_BYTES;
        #pragma unroll
        for (int i = 0; i < OPC; ++i)
            bulk_ld(dst + i * 512, src + (size_t)i * (IN_F * 4), 512, mb);
    };

    if (tid == 0) {
        issue(0, 0); issue(1, 1); issue(2, 2);
    }

    u64 acc[OPW][BATCH];
    #pragma unroll
    for (int o = 0; o < OPW; ++o)
        #pragma unroll
        for (int b = 0; b < BATCH; ++b) acc[o][b] = 0ull;

    int scur = 0, fph = 0, eph = 0;
    #pragma unroll 1
    for (int g = 0; g < NG; ++g) {
        mbar_wait(full_base + scur * 8, fph);

        // convert this warp's 4 rows from smem: qs[o] = (s*q0,s*q1),(s*q2,s*q3)
        float4 sv = __ldg((const float4*)(sc + g * OUT_F + n0));
        u64 qs[OPW][2];
        {
            const float sa[OPW] = {sv.x, sv.y, sv.z, sv.w};
            const int* wp = ws + (scur * OPC + warp * OPW) * GS + klo;
            #pragma unroll
            for (int o = 0; o < OPW; ++o) {
                int4 q = *(const int4*)(wp + o * GS);
                u64 s2 = pack2(sa[o], sa[o]);
                qs[o][0] = mul2(pack2((float)q.x, (float)q.y), s2);
                qs[o][1] = mul2(pack2((float)q.z, (float)q.w), s2);
            }
        }

        // math: x pairs from L1-resident x (weights never touch L1 now)
        const float* xg = x + g * GS + klo;
        #pragma unroll
        for (int b = 0; b < BATCH; ++b) {
            ulonglong2 xv = ldg_x2(xg + b * IN_F);
            #pragma unroll
            for (int o = 0; o < OPW; ++o) {
                acc[o][b] = fma2(xv.x, qs[o][0], acc[o][b]);
                acc[o][b] = fma2(xv.y, qs[o][1], acc[o][b]);
            }
        }

        mbar_arrive(empt_base + scur * 8);

        if (tid == 0 && g + NSTG < NG) {
            mbar_wait(empt_base + scur * 8, eph);   // all 128 done with this stage
            issue(g + NSTG, scur);
        }

        if (++scur == NSTG) { scur = 0; fph ^= 1; eph ^= 1; }
    }

    // ---- pair-halves add, butterfly across 32 lanes ----
    float r[OPW][BATCH];
    #pragma unroll
    for (int o = 0; o < OPW; ++o)
        #pragma unroll
        for (int b = 0; b < BATCH; ++b) {
            float lo, hi; unpack2(acc[o][b], lo, hi);
            r[o][b] = lo + hi;
        }
    #pragma unroll
    for (int off = 16; off > 0; off >>= 1)
        #pragma unroll
        for (int o = 0; o < OPW; ++o)
            #pragma unroll
            for (int b = 0; b < BATCH; ++b)
                r[o][b] += __shfl_xor_sync(0xffffffffu, r[o][b], off);

    if (lane == 0) {
        #pragma unroll
        for (int o = 0; o < OPW; ++o)
            #pragma unroll
            for (int b = 0; b < BATCH; ++b)
                bounce[warp][o * BATCH + b] = r[o][b];
    }
    __syncwarp();

    // 32 results per warp, one per lane; fold in zero/offset term
    const int o = lane >> 3, b = lane & 7;
    const int n = n0 + o;
    float offt = 0.f;
    #pragma unroll
    for (int g2 = 0; g2 < NG; ++g2) {
        float s = __ldg(sc + g2 * OUT_F + n);
        float z = __ldg(zr + g2 * OUT_F + n);
        offt = fmaf(z - 8.f * s, g_sx[b * NG + g2], offt);
    }
    out[b * OUT_F + n] = bounce[warp][lane] + offt;
}

extern "C" void kernel_launch(void* const* d_in, const int* in_sizes, int n_in,
                              void* d_out, int out_size) {
    const float* x  = (const float*)d_in[0];
    const int*   qw = (const int*)d_in[1];
    const float* sc = (const float*)d_in[2];
    const float* zr = (const float*)d_in[3];
    float* out = (float*)d_out;

    prep_kernel<<<32, 256>>>(x);
    w4a32_main<<<OUT_F / OPC, TPB>>>(x, qw, sc, zr, out);   // 768 x 128
}